// round 3
// baseline (speedup 1.0000x reference)
#include <cuda_runtime.h>
#include <math.h>

#define Bv 32
#define Tv 8
#define BT 256
#define Ev 128
#define Fv 512
#define NHEADv 8
#define DHv 16
#define NSPv 6
#define NUMCLSv 4
#define HFEATv 128
#define WINDOWv 4
#define NLAYERSv 2
#define MAXL 134
#define MAXM (BT*MAXL)

// ---------------- scratch (device globals; no allocation allowed) ----------------
__device__ float g_X[MAXM*Ev];
__device__ float g_H[MAXM*Ev];
__device__ float g_Qb[MAXM*Ev];
__device__ float g_Kb[MAXM*Ev];
__device__ float g_Vb[MAXM*Ev];
__device__ float g_Ob[MAXM*Ev];
__device__ float g_FF[MAXM*Fv];
__device__ float g_CLS[BT*NUMCLSv*Ev];

// ---------------- build sequence: specials + grouped mean pooling ----------------
__global__ void build_x_kernel(const float* __restrict__ emb,
                               const float* __restrict__ cls,
                               const float* __restrict__ glb,
                               float* __restrict__ X, int L, int g) {
    int idx = blockIdx.x * blockDim.x + threadIdx.x;
    int total = BT * L * Ev;
    if (idx >= total) return;
    int e  = idx & (Ev - 1);
    int l  = (idx >> 7) % L;
    int bt = idx / (L * Ev);
    float v;
    if (l < NUMCLSv) {
        v = cls[l * Ev + e];
    } else if (l < NSPv) {
        v = glb[(l - NUMCLSv) * Ev + e];
    } else {
        int k = l - NSPv;
        const float* base = emb + ((size_t)bt * (NSPv + HFEATv) + NSPv + (size_t)k * g) * Ev + e;
        float s = 0.f;
        for (int j = 0; j < g; j++) s += base[(size_t)j * Ev];
        v = s / (float)g;
    }
    X[idx] = v;
}

// ---------------- row layernorm over E=128 (one row per block, 128 thr) ----------
__global__ void ln_kernel(const float* __restrict__ X, const float* __restrict__ gw,
                          const float* __restrict__ bw, float* __restrict__ Hout) {
    int row = blockIdx.x;
    int t = threadIdx.x;
    float v = X[(size_t)row * Ev + t];
    __shared__ float sh[4];
    float s = v;
    #pragma unroll
    for (int o = 16; o > 0; o >>= 1) s += __shfl_xor_sync(0xffffffffu, s, o);
    if ((t & 31) == 0) sh[t >> 5] = s;
    __syncthreads();
    float mean = (sh[0] + sh[1] + sh[2] + sh[3]) * (1.f / Ev);
    float d = v - mean;
    float s2 = d * d;
    #pragma unroll
    for (int o = 16; o > 0; o >>= 1) s2 += __shfl_xor_sync(0xffffffffu, s2, o);
    __syncthreads();
    if ((t & 31) == 0) sh[t >> 5] = s2;
    __syncthreads();
    float var = (sh[0] + sh[1] + sh[2] + sh[3]) * (1.f / Ev);
    Hout[(size_t)row * Ev + t] = d * rsqrtf(var + 1e-5f) * gw[t] + bw[t];
}

// ---------------- tiled fp32 GEMM: C = A[M,K] @ W[K,N] + bias (+resid) ----------
// 64x64 tile per block (256 threads), 4x4 per thread. Requires M%64==0, N%64==0, K%16==0.
__global__ __launch_bounds__(256) void gemm_kernel(
        const float* __restrict__ A, const float* __restrict__ W,
        const float* __restrict__ bias, const float* __restrict__ resid,
        float* __restrict__ C, int M, int N, int K) {
    __shared__ float sA[16][65];
    __shared__ float sW[16][64];
    int tid = threadIdx.x;
    int tx = tid & 15, ty = tid >> 4;
    int m0 = blockIdx.y * 64, n0 = blockIdx.x * 64;
    float acc[4][4] = {};
    for (int k0 = 0; k0 < K; k0 += 16) {
        #pragma unroll
        for (int i = 0; i < 4; i++) {
            int el = tid + i * 256;
            int m = el >> 4, kk = el & 15;
            sA[kk][m] = A[(size_t)(m0 + m) * K + k0 + kk];
            int k2 = el >> 6, n2 = el & 63;
            sW[k2][n2] = W[(size_t)(k0 + k2) * N + n0 + n2];
        }
        __syncthreads();
        #pragma unroll
        for (int kk = 0; kk < 16; kk++) {
            float a[4], b[4];
            #pragma unroll
            for (int i = 0; i < 4; i++) a[i] = sA[kk][ty + 16 * i];
            #pragma unroll
            for (int j = 0; j < 4; j++) b[j] = sW[kk][tx + 16 * j];
            #pragma unroll
            for (int i = 0; i < 4; i++)
                #pragma unroll
                for (int j = 0; j < 4; j++) acc[i][j] += a[i] * b[j];
        }
        __syncthreads();
    }
    #pragma unroll
    for (int i = 0; i < 4; i++) {
        int m = m0 + ty + 16 * i;
        #pragma unroll
        for (int j = 0; j < 4; j++) {
            int n = n0 + tx + 16 * j;
            float v = acc[i][j] + bias[n];
            size_t ci = (size_t)m * N + n;
            if (resid) v += resid[ci];
            C[ci] = v;
        }
    }
}

// ---------------- RoPE applied to Q and K in place ----------------
__global__ void rope_kernel(float* __restrict__ Q, float* __restrict__ Kp, int L) {
    int idx = blockIdx.x * blockDim.x + threadIdx.x;
    int total = BT * L * NHEADv * 8;
    if (idx >= total) return;
    int j  = idx & 7;
    int h  = (idx >> 3) & 7;
    int l  = (idx >> 6) % L;
    int bt = idx / (L * 64);
    float inv = powf(100000.0f, -(float)j / 8.0f);
    float ang = (float)l * inv;
    float c = cosf(ang), s = sinf(ang);
    size_t base = ((size_t)(bt * L + l)) * Ev + h * DHv + j;
    float q1 = Q[base], q2 = Q[base + 8];
    Q[base]     = q1 * c - q2 * s;
    Q[base + 8] = q1 * s + q2 * c;
    float k1 = Kp[base], k2 = Kp[base + 8];
    Kp[base]     = k1 * c - k2 * s;
    Kp[base + 8] = k1 * s + k2 * c;
}

// ---------------- fused attention: one block per (bt, head) ----------------
__global__ __launch_bounds__(128) void attn_kernel(
        const float* __restrict__ Q, const float* __restrict__ Kx,
        const float* __restrict__ V, float* __restrict__ O, int L) {
    int h  = blockIdx.x & 7;
    int bt = blockIdx.x >> 3;
    __shared__ float Ksh[MAXL][DHv];
    __shared__ float Vsh[MAXL][DHv];
    __shared__ float sc[MAXL];
    __shared__ float qsh[DHv];
    __shared__ float red[4];
    __shared__ float part[8][16];
    int t = threadIdx.x;

    for (int i = t; i < L * DHv; i += 128) {
        int m = i >> 4, d = i & 15;
        size_t gi = ((size_t)(bt * L + m)) * Ev + h * DHv + d;
        Ksh[m][d] = Kx[gi];
        Vsh[m][d] = V[gi];
    }
    __syncthreads();

    for (int lq = 0; lq < L; lq++) {
        if (t < DHv) qsh[t] = Q[((size_t)(bt * L + lq)) * Ev + h * DHv + t];
        __syncthreads();
        for (int m = t; m < L; m += 128) {
            float s = 0.f;
            #pragma unroll
            for (int d = 0; d < DHv; d++) s += qsh[d] * Ksh[m][d];
            s *= 0.25f;  // 1/sqrt(16)
            int diff = lq - m; if (diff < 0) diff = -diff;
            bool allowed = (diff <= WINDOWv) || (lq < NSPv) || (m < NSPv);
            sc[m] = allowed ? s : -1e9f;
        }
        __syncthreads();
        // row max
        float mx = -1e30f;
        for (int m = t; m < L; m += 128) mx = fmaxf(mx, sc[m]);
        #pragma unroll
        for (int o = 16; o > 0; o >>= 1) mx = fmaxf(mx, __shfl_xor_sync(0xffffffffu, mx, o));
        if ((t & 31) == 0) red[t >> 5] = mx;
        __syncthreads();
        mx = fmaxf(fmaxf(red[0], red[1]), fmaxf(red[2], red[3]));
        __syncthreads();
        // exp + sum
        float sum = 0.f;
        for (int m = t; m < L; m += 128) {
            float e = expf(sc[m] - mx);
            sc[m] = e;
            sum += e;
        }
        #pragma unroll
        for (int o = 16; o > 0; o >>= 1) sum += __shfl_xor_sync(0xffffffffu, sum, o);
        if ((t & 31) == 0) red[t >> 5] = sum;
        __syncthreads();
        float denom = red[0] + red[1] + red[2] + red[3];
        // weighted sum of V: 8 groups x 16 dims
        int d = t & 15, grp = t >> 4;
        float p = 0.f;
        for (int m = grp; m < L; m += 8) p += sc[m] * Vsh[m][d];
        part[grp][d] = p;
        __syncthreads();
        if (t < DHv) {
            float o = 0.f;
            #pragma unroll
            for (int g2 = 0; g2 < 8; g2++) o += part[g2][t];
            O[((size_t)(bt * L + lq)) * Ev + h * DHv + t] = o / denom;
        }
        __syncthreads();
    }
}

// ---------------- tanh GELU (jax.nn.gelu default approximate=True) ---------------
__global__ void gelu_kernel(float* __restrict__ X, int n) {
    int i = blockIdx.x * blockDim.x + threadIdx.x;
    if (i >= n) return;
    float x = X[i];
    float c = x + 0.044715f * x * x * x;
    X[i] = 0.5f * x * (1.f + tanhf(0.7978845608028654f * c));
}

// ---------------- CLS accumulate across scales ----------------
__global__ void cls_acc_kernel(const float* __restrict__ X, float* __restrict__ acc,
                               int L, int init) {
    int idx = blockIdx.x * blockDim.x + threadIdx.x;
    if (idx >= BT * NUMCLSv * Ev) return;
    int e  = idx & (Ev - 1);
    int c  = (idx >> 7) & 3;
    int bt = idx >> 9;
    float v = X[((size_t)(bt * L + c)) * Ev + e];
    if (init) acc[idx] = v;
    else      acc[idx] += v;
}

// ---------------- final: mean over scales + LN + write ----------------
__global__ void final_kernel(const float* __restrict__ acc, const float* __restrict__ og,
                             const float* __restrict__ ob, float* __restrict__ out) {
    int row = blockIdx.x;   // bt*4 + c, 1024 rows
    int t = threadIdx.x;
    float v = acc[(size_t)row * Ev + t] * (1.f / 3.f);
    __shared__ float sh[4];
    float s = v;
    #pragma unroll
    for (int o = 16; o > 0; o >>= 1) s += __shfl_xor_sync(0xffffffffu, s, o);
    if ((t & 31) == 0) sh[t >> 5] = s;
    __syncthreads();
    float mean = (sh[0] + sh[1] + sh[2] + sh[3]) * (1.f / Ev);
    float d = v - mean;
    float s2 = d * d;
    #pragma unroll
    for (int o = 16; o > 0; o >>= 1) s2 += __shfl_xor_sync(0xffffffffu, s2, o);
    __syncthreads();
    if ((t & 31) == 0) sh[t >> 5] = s2;
    __syncthreads();
    float var = (sh[0] + sh[1] + sh[2] + sh[3]) * (1.f / Ev);
    out[(size_t)row * Ev + t] = d * rsqrtf(var + 1e-5f) * og[t] + ob[t];
}

// ---------------- host orchestration ----------------
extern "C" void kernel_launch(void* const* d_in, const int* in_sizes, int n_in,
                              void* d_out, int out_size) {
    const float* emb   = (const float*)d_in[0];
    const float* cls   = (const float*)d_in[1];
    const float* glb   = (const float*)d_in[2];
    const float* Wq    = (const float*)d_in[3];
    const float* bq    = (const float*)d_in[4];
    const float* Wk    = (const float*)d_in[5];
    const float* bk    = (const float*)d_in[6];
    const float* Wv    = (const float*)d_in[7];
    const float* bv    = (const float*)d_in[8];
    const float* Wo    = (const float*)d_in[9];
    const float* bo    = (const float*)d_in[10];
    const float* ln1g  = (const float*)d_in[11];
    const float* ln1b  = (const float*)d_in[12];
    const float* ln2g  = (const float*)d_in[13];
    const float* ln2b  = (const float*)d_in[14];
    const float* W1    = (const float*)d_in[15];
    const float* b1    = (const float*)d_in[16];
    const float* W2    = (const float*)d_in[17];
    const float* b2    = (const float*)d_in[18];
    const float* outg  = (const float*)d_in[19];
    const float* outb  = (const float*)d_in[20];
    float* out = (float*)d_out;

    float *X, *H, *Qb, *Kb, *Vb, *Ob, *FF, *CLSa;
    cudaGetSymbolAddress((void**)&X,    g_X);
    cudaGetSymbolAddress((void**)&H,    g_H);
    cudaGetSymbolAddress((void**)&Qb,   g_Qb);
    cudaGetSymbolAddress((void**)&Kb,   g_Kb);
    cudaGetSymbolAddress((void**)&Vb,   g_Vb);
    cudaGetSymbolAddress((void**)&Ob,   g_Ob);
    cudaGetSymbolAddress((void**)&FF,   g_FF);
    cudaGetSymbolAddress((void**)&CLSa, g_CLS);

    static const int GS[3] = {1, 4, 8};
    for (int s = 0; s < 3; s++) {
        int g = GS[s];
        int Kgrp = HFEATv / g;
        int L = NSPv + Kgrp;
        int M = BT * L;

        {
            int total = M * Ev;
            build_x_kernel<<<(total + 255) / 256, 256>>>(emb, cls, glb, X, L, g);
        }

        for (int l = 0; l < NLAYERSv; l++) {
            int wi = s * NLAYERSv + l;
            const float* wq = Wq + (size_t)wi * Ev * Ev;
            const float* wk = Wk + (size_t)wi * Ev * Ev;
            const float* wv = Wv + (size_t)wi * Ev * Ev;
            const float* wo = Wo + (size_t)wi * Ev * Ev;
            const float* w1 = W1 + (size_t)wi * Ev * Fv;
            const float* w2 = W2 + (size_t)wi * Fv * Ev;

            ln_kernel<<<M, 128>>>(X, ln1g + (size_t)wi * Ev, ln1b + (size_t)wi * Ev, H);

            dim3 gEE(Ev / 64, M / 64);
            gemm_kernel<<<gEE, 256>>>(H, wq, bq + (size_t)wi * Ev, nullptr, Qb, M, Ev, Ev);
            gemm_kernel<<<gEE, 256>>>(H, wk, bk + (size_t)wi * Ev, nullptr, Kb, M, Ev, Ev);
            gemm_kernel<<<gEE, 256>>>(H, wv, bv + (size_t)wi * Ev, nullptr, Vb, M, Ev, Ev);

            {
                int total = BT * L * NHEADv * 8;
                rope_kernel<<<(total + 255) / 256, 256>>>(Qb, Kb, L);
            }

            attn_kernel<<<BT * NHEADv, 128>>>(Qb, Kb, Vb, Ob, L);

            gemm_kernel<<<gEE, 256>>>(Ob, wo, bo + (size_t)wi * Ev, X, X, M, Ev, Ev);

            ln_kernel<<<M, 128>>>(X, ln2g + (size_t)wi * Ev, ln2b + (size_t)wi * Ev, H);

            dim3 gEF(Fv / 64, M / 64);
            gemm_kernel<<<gEF, 256>>>(H, w1, b1 + (size_t)wi * Fv, nullptr, FF, M, Fv, Ev);

            {
                int total = M * Fv;
                gelu_kernel<<<(total + 255) / 256, 256>>>(FF, total);
            }

            gemm_kernel<<<gEE, 256>>>(FF, w2, b2 + (size_t)wi * Ev, X, X, M, Ev, Fv);
        }

        {
            int total = BT * NUMCLSv * Ev;
            cls_acc_kernel<<<(total + 255) / 256, 256>>>(X, CLSa, L, s == 0 ? 1 : 0);
        }
    }

    final_kernel<<<BT * NUMCLSv, 128>>>(CLSa, outg, outb, out);
}

// round 8
// speedup vs baseline: 2.2397x; 2.2397x over previous
#include <cuda_runtime.h>
#include <math.h>

#define Bv 32
#define Tv 8
#define BT 256
#define Ev 128
#define Fv 512
#define NHEADv 8
#define DHv 16
#define NSPv 6
#define NUMCLSv 4
#define HFEATv 128
#define WINDOWv 4
#define NLAYERSv 2
#define MAXL 134
#define MAXM (BT*MAXL)

// ---------------- scratch (device globals; no allocation allowed) ----------------
__device__ float g_X[MAXM*Ev];
__device__ float g_H[MAXM*Ev];
__device__ float g_QKV[MAXM*384];
__device__ float g_Ob[MAXM*Ev];
__device__ float g_FF[MAXM*Fv];
__device__ float g_CLS[BT*NUMCLSv*Ev];
__device__ float g_Wqkv[Ev*384];
__device__ float g_bqkv[384];

// ---------------- build sequence: specials + grouped mean pooling ----------------
__global__ void build_x_kernel(const float* __restrict__ emb,
                               const float* __restrict__ cls,
                               const float* __restrict__ glb,
                               float* __restrict__ X, int L, int g) {
    int idx = blockIdx.x * blockDim.x + threadIdx.x;
    int total = BT * L * Ev;
    if (idx >= total) return;
    int e  = idx & (Ev - 1);
    int l  = (idx >> 7) % L;
    int bt = idx / (L * Ev);
    float v;
    if (l < NUMCLSv) {
        v = cls[l * Ev + e];
    } else if (l < NSPv) {
        v = glb[(l - NUMCLSv) * Ev + e];
    } else {
        int k = l - NSPv;
        const float* base = emb + ((size_t)bt * (NSPv + HFEATv) + NSPv + (size_t)k * g) * Ev + e;
        float s = 0.f;
        for (int j = 0; j < g; j++) s += base[(size_t)j * Ev];
        v = s / (float)g;
    }
    X[idx] = v;
}

// ---------------- row layernorm over E=128 (one row per block, 128 thr) ----------
__global__ void ln_kernel(const float* __restrict__ X, const float* __restrict__ gw,
                          const float* __restrict__ bw, float* __restrict__ Hout) {
    int row = blockIdx.x;
    int t = threadIdx.x;
    float v = X[(size_t)row * Ev + t];
    __shared__ float sh[4];
    float s = v;
    #pragma unroll
    for (int o = 16; o > 0; o >>= 1) s += __shfl_xor_sync(0xffffffffu, s, o);
    if ((t & 31) == 0) sh[t >> 5] = s;
    __syncthreads();
    float mean = (sh[0] + sh[1] + sh[2] + sh[3]) * (1.f / Ev);
    float d = v - mean;
    float s2 = d * d;
    #pragma unroll
    for (int o = 16; o > 0; o >>= 1) s2 += __shfl_xor_sync(0xffffffffu, s2, o);
    __syncthreads();
    if ((t & 31) == 0) sh[t >> 5] = s2;
    __syncthreads();
    float var = (sh[0] + sh[1] + sh[2] + sh[3]) * (1.f / Ev);
    Hout[(size_t)row * Ev + t] = d * rsqrtf(var + 1e-5f) * gw[t] + bw[t];
}

// ---------------- pack QKV weights/biases into one [E,384] matrix ----------------
__global__ void pack_qkv_kernel(const float* __restrict__ Wq, const float* __restrict__ Wk,
                                const float* __restrict__ Wv, const float* __restrict__ bq,
                                const float* __restrict__ bk, const float* __restrict__ bv,
                                float* __restrict__ Wp, float* __restrict__ bp) {
    int idx = blockIdx.x * blockDim.x + threadIdx.x;
    if (idx < 384) {
        int which = idx >> 7, col = idx & 127;
        bp[idx] = (which == 0) ? bq[col] : (which == 1) ? bk[col] : bv[col];
    }
    if (idx < Ev * 384) {
        int k = idx / 384, n = idx % 384;
        int which = n >> 7, col = n & 127;
        const float* src = (which == 0) ? Wq : (which == 1) ? Wk : Wv;
        Wp[idx] = src[k * Ev + col];
    }
}

// ---------------- GEMM: 128x128 tile, 8x8/thread, double-buffered -----------------
// C[M,N] = A[M,K] @ W[K,N] + bias (+resid) (opt GELU). M%128==0, N%128==0, K%8==0.
template<int DO_GELU>
__global__ __launch_bounds__(256, 2) void gemm128_kernel(
        const float* __restrict__ A, const float* __restrict__ W,
        const float* __restrict__ bias, const float* __restrict__ resid,
        float* __restrict__ C, int M, int N, int K) {
    __shared__ float sA[2][8][132];
    __shared__ float sW[2][8][128];
    int tid = threadIdx.x;
    int tx = tid & 15;       // n sub-tile
    int ty = tid >> 4;       // m sub-tile
    int m0 = blockIdx.y * 128, n0 = blockIdx.x * 128;

    // loader coords
    int ar = tid >> 1;               // A row 0..127
    int ah = (tid & 1) * 4;          // A k-offset 0 or 4
    int wr = tid >> 5;               // W k-row 0..7
    int wc = (tid & 31) * 4;         // W col

    const float* Aptr = A + (size_t)(m0 + ar) * K + ah;
    const float* Wptr = W + (size_t)wr * N + n0 + wc;

    int nk = K >> 3;
    float4 aReg = *(const float4*)Aptr;
    float4 wReg = *(const float4*)Wptr;

    float acc[8][8];
    #pragma unroll
    for (int i = 0; i < 8; i++)
        #pragma unroll
        for (int j = 0; j < 8; j++) acc[i][j] = 0.f;

    // stage chunk 0
    sA[0][ah + 0][ar] = aReg.x;
    sA[0][ah + 1][ar] = aReg.y;
    sA[0][ah + 2][ar] = aReg.z;
    sA[0][ah + 3][ar] = aReg.w;
    *(float4*)&sW[0][wr][wc] = wReg;
    __syncthreads();

    for (int c = 0; c < nk; c++) {
        int cur = c & 1, nxt = cur ^ 1;
        if (c + 1 < nk) {
            aReg = *(const float4*)(Aptr + (c + 1) * 8);
            wReg = *(const float4*)(Wptr + (size_t)(c + 1) * 8 * N);
        }
        #pragma unroll
        for (int kk = 0; kk < 8; kk++) {
            float a[8], b[8];
            *(float4*)&a[0] = *(const float4*)&sA[cur][kk][ty * 4];
            *(float4*)&a[4] = *(const float4*)&sA[cur][kk][64 + ty * 4];
            *(float4*)&b[0] = *(const float4*)&sW[cur][kk][tx * 4];
            *(float4*)&b[4] = *(const float4*)&sW[cur][kk][64 + tx * 4];
            #pragma unroll
            for (int i = 0; i < 8; i++)
                #pragma unroll
                for (int j = 0; j < 8; j++) acc[i][j] += a[i] * b[j];
        }
        if (c + 1 < nk) {
            sA[nxt][ah + 0][ar] = aReg.x;
            sA[nxt][ah + 1][ar] = aReg.y;
            sA[nxt][ah + 2][ar] = aReg.z;
            sA[nxt][ah + 3][ar] = aReg.w;
            *(float4*)&sW[nxt][wr][wc] = wReg;
        }
        __syncthreads();
    }

    // epilogue
    #pragma unroll
    for (int i = 0; i < 8; i++) {
        int m = m0 + ((i < 4) ? (ty * 4 + i) : (64 + ty * 4 + i - 4));
        #pragma unroll
        for (int jj = 0; jj < 2; jj++) {
            int nb = n0 + ((jj == 0) ? tx * 4 : 64 + tx * 4);
            float4 bv4 = *(const float4*)&bias[nb];
            float4 v;
            v.x = acc[i][jj * 4 + 0] + bv4.x;
            v.y = acc[i][jj * 4 + 1] + bv4.y;
            v.z = acc[i][jj * 4 + 2] + bv4.z;
            v.w = acc[i][jj * 4 + 3] + bv4.w;
            if (resid) {
                float4 r4 = *(const float4*)&resid[(size_t)m * N + nb];
                v.x += r4.x; v.y += r4.y; v.z += r4.z; v.w += r4.w;
            }
            if (DO_GELU) {
                #pragma unroll
                for (int q = 0; q < 4; q++) {
                    float x = ((float*)&v)[q];
                    float cc = x + 0.044715f * x * x * x;
                    ((float*)&v)[q] = 0.5f * x * (1.f + tanhf(0.7978845608028654f * cc));
                }
            }
            *(float4*)&C[(size_t)m * N + nb] = v;
        }
    }
}

// ---------------- attention: warp-per-query, rope fused, sparse-aware ------------
// QKV packed [M][384] (Q|K|V). One block per (bt, head), 8 warps.
__global__ __launch_bounds__(256) void attn2_kernel(
        const float* __restrict__ QKV, float* __restrict__ O, int L) {
    int h  = blockIdx.x & 7;
    int bt = blockIdx.x >> 3;
    __shared__ float Ksh[MAXL][20];
    __shared__ float Vsh[MAXL][16];
    __shared__ float esh[8][MAXL];
    __shared__ float invs[8];
    int tid = threadIdx.x;
    int w = tid >> 5, lane = tid & 31;

    if (tid < 8) invs[tid] = powf(100000.0f, -(float)tid / 8.0f);
    __syncthreads();

    // load K (with RoPE) and V into smem
    for (int i = tid; i < L * 8; i += 256) {
        int m = i >> 3, j = i & 7;
        size_t base = ((size_t)(bt * L + m)) * 384 + h * DHv + j;
        float k1 = QKV[base + 128], k2 = QKV[base + 128 + 8];
        float sv, cv;
        sincosf((float)m * invs[j], &sv, &cv);
        Ksh[m][j]     = k1 * cv - k2 * sv;
        Ksh[m][j + 8] = k1 * sv + k2 * cv;
        Vsh[m][j]     = QKV[base + 256];
        Vsh[m][j + 8] = QKV[base + 256 + 8];
    }
    __syncthreads();

    for (int lq = w; lq < L; lq += 8) {
        // load q (all lanes) and apply RoPE
        const float* qp = QKV + (size_t)(bt * L + lq) * 384 + h * DHv;
        float q[16];
        *(float4*)&q[0]  = *(const float4*)&qp[0];
        *(float4*)&q[4]  = *(const float4*)&qp[4];
        *(float4*)&q[8]  = *(const float4*)&qp[8];
        *(float4*)&q[12] = *(const float4*)&qp[12];
        float mys = 0.f, myc = 1.f;
        if (lane < 8) sincosf((float)lq * invs[lane], &mys, &myc);
        #pragma unroll
        for (int j = 0; j < 8; j++) {
            float cv = __shfl_sync(0xffffffffu, myc, j);
            float sv = __shfl_sync(0xffffffffu, mys, j);
            float q1 = q[j], q2 = q[j + 8];
            q[j]     = q1 * cv - q2 * sv;
            q[j + 8] = q1 * sv + q2 * cv;
        }

        if (lq >= NSPv) {
            // sparse path: allowed = specials (6) + window [lo,hi]; cnt <= 15
            int lo = lq - WINDOWv; if (lo < NSPv) lo = NSPv;
            int hi = lq + WINDOWv; if (hi > L - 1) hi = L - 1;
            int cnt = 6 + (hi - lo + 1);
            int m = (lane < 6) ? lane : (lo + lane - 6);
            if (m > L - 1) m = L - 1;           // clamp; masked below
            bool act = lane < cnt;
            float s = -1e30f;
            if (act) {
                float d = 0.f;
                #pragma unroll
                for (int dd = 0; dd < 16; dd++) d += q[dd] * Ksh[m][dd];
                s = d * 0.25f;
            }
            float mx = s;
            #pragma unroll
            for (int o = 16; o > 0; o >>= 1) mx = fmaxf(mx, __shfl_xor_sync(0xffffffffu, mx, o));
            float e = act ? expf(s - mx) : 0.f;
            float sum = e;
            #pragma unroll
            for (int o = 16; o > 0; o >>= 1) sum += __shfl_xor_sync(0xffffffffu, sum, o);
            // AV: uniform fixed-trip loop; shfl executed by ALL lanes every
            // iteration (divergent-trip shfl was the R3 crash). cnt <= 15.
            int d = lane & 15;
            float ov = 0.f;
            #pragma unroll
            for (int i = 0; i < 15; i++) {
                float ei = __shfl_sync(0xffffffffu, e, i);
                if (i < cnt) {
                    int mi = (i < 6) ? i : (lo + i - 6);
                    ov += ei * Vsh[mi][d];
                }
            }
            if (lane < 16)
                O[((size_t)(bt * L + lq)) * Ev + h * DHv + lane] = ov / sum;
        } else {
            // dense path (lq < NSP: everything allowed)
            float mx = -1e30f;
            for (int m = lane; m < L; m += 32) {
                float d = 0.f;
                #pragma unroll
                for (int dd = 0; dd < 16; dd++) d += q[dd] * Ksh[m][dd];
                d *= 0.25f;
                esh[w][m] = d;
                mx = fmaxf(mx, d);
            }
            #pragma unroll
            for (int o = 16; o > 0; o >>= 1) mx = fmaxf(mx, __shfl_xor_sync(0xffffffffu, mx, o));
            float sum = 0.f;
            for (int m = lane; m < L; m += 32) {
                float e = expf(esh[w][m] - mx);
                esh[w][m] = e;
                sum += e;
            }
            #pragma unroll
            for (int o = 16; o > 0; o >>= 1) sum += __shfl_xor_sync(0xffffffffu, sum, o);
            __syncwarp();
            int d = lane & 15, half = lane >> 4;
            float ov = 0.f;
            for (int m = half; m < L; m += 2) ov += esh[w][m] * Vsh[m][d];
            ov += __shfl_xor_sync(0xffffffffu, ov, 16);
            if (lane < 16)
                O[((size_t)(bt * L + lq)) * Ev + h * DHv + lane] = ov / sum;
            __syncwarp();
        }
    }
}

// ---------------- CLS accumulate across scales ----------------
__global__ void cls_acc_kernel(const float* __restrict__ X, float* __restrict__ acc,
                               int L, int init) {
    int idx = blockIdx.x * blockDim.x + threadIdx.x;
    if (idx >= BT * NUMCLSv * Ev) return;
    int e  = idx & (Ev - 1);
    int c  = (idx >> 7) & 3;
    int bt = idx >> 9;
    float v = X[((size_t)(bt * L + c)) * Ev + e];
    if (init) acc[idx] = v;
    else      acc[idx] += v;
}

// ---------------- final: mean over scales + LN + write ----------------
__global__ void final_kernel(const float* __restrict__ acc, const float* __restrict__ og,
                             const float* __restrict__ ob, float* __restrict__ out) {
    int row = blockIdx.x;
    int t = threadIdx.x;
    float v = acc[(size_t)row * Ev + t] * (1.f / 3.f);
    __shared__ float sh[4];
    float s = v;
    #pragma unroll
    for (int o = 16; o > 0; o >>= 1) s += __shfl_xor_sync(0xffffffffu, s, o);
    if ((t & 31) == 0) sh[t >> 5] = s;
    __syncthreads();
    float mean = (sh[0] + sh[1] + sh[2] + sh[3]) * (1.f / Ev);
    float d = v - mean;
    float s2 = d * d;
    #pragma unroll
    for (int o = 16; o > 0; o >>= 1) s2 += __shfl_xor_sync(0xffffffffu, s2, o);
    __syncthreads();
    if ((t & 31) == 0) sh[t >> 5] = s2;
    __syncthreads();
    float var = (sh[0] + sh[1] + sh[2] + sh[3]) * (1.f / Ev);
    out[(size_t)row * Ev + t] = d * rsqrtf(var + 1e-5f) * og[t] + ob[t];
}

// ---------------- host orchestration ----------------
extern "C" void kernel_launch(void* const* d_in, const int* in_sizes, int n_in,
                              void* d_out, int out_size) {
    const float* emb   = (const float*)d_in[0];
    const float* cls   = (const float*)d_in[1];
    const float* glb   = (const float*)d_in[2];
    const float* Wq    = (const float*)d_in[3];
    const float* bq    = (const float*)d_in[4];
    const float* Wk    = (const float*)d_in[5];
    const float* bk    = (const float*)d_in[6];
    const float* Wv    = (const float*)d_in[7];
    const float* bv    = (const float*)d_in[8];
    const float* Wo    = (const float*)d_in[9];
    const float* bo    = (const float*)d_in[10];
    const float* ln1g  = (const float*)d_in[11];
    const float* ln1b  = (const float*)d_in[12];
    const float* ln2g  = (const float*)d_in[13];
    const float* ln2b  = (const float*)d_in[14];
    const float* W1    = (const float*)d_in[15];
    const float* b1    = (const float*)d_in[16];
    const float* W2    = (const float*)d_in[17];
    const float* b2    = (const float*)d_in[18];
    const float* outg  = (const float*)d_in[19];
    const float* outb  = (const float*)d_in[20];
    float* out = (float*)d_out;

    float *X, *H, *QKV, *Ob, *FF, *CLSa, *Wp, *bp;
    cudaGetSymbolAddress((void**)&X,    g_X);
    cudaGetSymbolAddress((void**)&H,    g_H);
    cudaGetSymbolAddress((void**)&QKV,  g_QKV);
    cudaGetSymbolAddress((void**)&Ob,   g_Ob);
    cudaGetSymbolAddress((void**)&FF,   g_FF);
    cudaGetSymbolAddress((void**)&CLSa, g_CLS);
    cudaGetSymbolAddress((void**)&Wp,   g_Wqkv);
    cudaGetSymbolAddress((void**)&bp,   g_bqkv);

    static const int GS[3] = {1, 4, 8};
    for (int s = 0; s < 3; s++) {
        int g = GS[s];
        int Kgrp = HFEATv / g;
        int L = NSPv + Kgrp;
        int M = BT * L;

        {
            int total = M * Ev;
            build_x_kernel<<<(total + 255) / 256, 256>>>(emb, cls, glb, X, L, g);
        }

        for (int l = 0; l < NLAYERSv; l++) {
            int wi = s * NLAYERSv + l;
            const float* wq = Wq + (size_t)wi * Ev * Ev;
            const float* wk = Wk + (size_t)wi * Ev * Ev;
            const float* wv = Wv + (size_t)wi * Ev * Ev;
            const float* wo = Wo + (size_t)wi * Ev * Ev;
            const float* w1 = W1 + (size_t)wi * Ev * Fv;
            const float* w2 = W2 + (size_t)wi * Fv * Ev;

            pack_qkv_kernel<<<(Ev * 384 + 255) / 256, 256>>>(
                wq, wk, wv, bq + (size_t)wi * Ev, bk + (size_t)wi * Ev,
                bv + (size_t)wi * Ev, Wp, bp);

            ln_kernel<<<M, 128>>>(X, ln1g + (size_t)wi * Ev, ln1b + (size_t)wi * Ev, H);

            // fused QKV gemm: [M,128] @ [128,384]
            {
                dim3 gr(384 / 128, M / 128);
                gemm128_kernel<0><<<gr, 256>>>(H, Wp, bp, nullptr, QKV, M, 384, Ev);
            }

            attn2_kernel<<<BT * NHEADv, 256>>>(QKV, Ob, L);

            {
                dim3 gr(1, M / 128);
                gemm128_kernel<0><<<gr, 256>>>(Ob, wo, bo + (size_t)wi * Ev, X, X, M, Ev, Ev);
            }

            ln_kernel<<<M, 128>>>(X, ln2g + (size_t)wi * Ev, ln2b + (size_t)wi * Ev, H);

            {
                dim3 gr(Fv / 128, M / 128);
                gemm128_kernel<1><<<gr, 256>>>(H, w1, b1 + (size_t)wi * Fv, nullptr, FF, M, Fv, Ev);
            }
            {
                dim3 gr(1, M / 128);
                gemm128_kernel<0><<<gr, 256>>>(FF, w2, b2 + (size_t)wi * Ev, X, X, M, Ev, Fv);
            }
        }

        {
            int total = BT * NUMCLSv * Ev;
            cls_acc_kernel<<<(total + 255) / 256, 256>>>(X, CLSa, L, s == 0 ? 1 : 0);
        }
    }

    final_kernel<<<BT * NUMCLSv, 128>>>(CLSa, outg, outb, out);
}

// round 11
// speedup vs baseline: 3.2330x; 1.4434x over previous
#include <cuda_runtime.h>
#include <math.h>
#include <stdint.h>

#define Bv 32
#define Tv 8
#define BT 256
#define Ev 128
#define Fv 512
#define NHEADv 8
#define DHv 16
#define NSPv 6
#define NUMCLSv 4
#define HFEATv 128
#define WINDOWv 4
#define NLAYERSv 2
#define MAXL 134
#define MAXM (BT*MAXL)

// ---------------- scratch (device globals; no allocation allowed) ----------------
__device__ float g_X[MAXM*Ev];
__device__ float g_H[MAXM*Ev];
__device__ float g_QKV[MAXM*384];
__device__ float g_Ob[MAXM*Ev];
__device__ float g_FF[MAXM*Fv];
__device__ float g_CLS[BT*NUMCLSv*Ev];
__device__ float g_Wqkv[Ev*384];
__device__ float g_bqkv[384];

// ---------------- helpers ----------------
__device__ __forceinline__ float to_tf32(float x) {
    uint32_t u;
    asm("cvt.rna.tf32.f32 %0, %1;" : "=r"(u) : "f"(x));
    return __uint_as_float(u);
}

// ---------------- build sequence: specials + grouped mean pooling ----------------
__global__ void build_x_kernel(const float* __restrict__ emb,
                               const float* __restrict__ cls,
                               const float* __restrict__ glb,
                               float* __restrict__ X, int L, int g) {
    int idx = blockIdx.x * blockDim.x + threadIdx.x;
    int total = BT * L * Ev;
    if (idx >= total) return;
    int e  = idx & (Ev - 1);
    int l  = (idx >> 7) % L;
    int bt = idx / (L * Ev);
    float v;
    if (l < NUMCLSv) {
        v = cls[l * Ev + e];
    } else if (l < NSPv) {
        v = glb[(l - NUMCLSv) * Ev + e];
    } else {
        int k = l - NSPv;
        const float* base = emb + ((size_t)bt * (NSPv + HFEATv) + NSPv + (size_t)k * g) * Ev + e;
        float s = 0.f;
        for (int j = 0; j < g; j++) s += base[(size_t)j * Ev];
        v = s / (float)g;
    }
    X[idx] = v;
}

// ---------------- row layernorm over E=128 (one row per block, 128 thr) ----------
__global__ void ln_kernel(const float* __restrict__ X, const float* __restrict__ gw,
                          const float* __restrict__ bw, float* __restrict__ Hout) {
    int row = blockIdx.x;
    int t = threadIdx.x;
    float v = X[(size_t)row * Ev + t];
    __shared__ float sh[4];
    float s = v;
    #pragma unroll
    for (int o = 16; o > 0; o >>= 1) s += __shfl_xor_sync(0xffffffffu, s, o);
    if ((t & 31) == 0) sh[t >> 5] = s;
    __syncthreads();
    float mean = (sh[0] + sh[1] + sh[2] + sh[3]) * (1.f / Ev);
    float d = v - mean;
    float s2 = d * d;
    #pragma unroll
    for (int o = 16; o > 0; o >>= 1) s2 += __shfl_xor_sync(0xffffffffu, s2, o);
    __syncthreads();
    if ((t & 31) == 0) sh[t >> 5] = s2;
    __syncthreads();
    float var = (sh[0] + sh[1] + sh[2] + sh[3]) * (1.f / Ev);
    Hout[(size_t)row * Ev + t] = d * rsqrtf(var + 1e-5f) * gw[t] + bw[t];
}

// ---------------- pack QKV weights/biases into one [E,384] matrix ----------------
__global__ void pack_qkv_kernel(const float* __restrict__ Wq, const float* __restrict__ Wk,
                                const float* __restrict__ Wv, const float* __restrict__ bq,
                                const float* __restrict__ bk, const float* __restrict__ bv,
                                float* __restrict__ Wp, float* __restrict__ bp) {
    int idx = blockIdx.x * blockDim.x + threadIdx.x;
    if (idx < 384) {
        int which = idx >> 7, col = idx & 127;
        bp[idx] = (which == 0) ? bq[col] : (which == 1) ? bk[col] : bv[col];
    }
    if (idx < Ev * 384) {
        int k = idx / 384, n = idx % 384;
        int which = n >> 7, col = n & 127;
        const float* src = (which == 0) ? Wq : (which == 1) ? Wk : Wv;
        Wp[idx] = src[k * Ev + col];
    }
}

// ---------------- TF32 tensor-core GEMM -------------------------------------------
// C[M,N] = A[M,K] @ W[K,N] + bias (+resid) (opt GELU).
// Block tile 128x128, 8 warps (warp tile 32x64 = 2 m16 x 8 n8, mma.m16n8k8.tf32).
// K chunked by 16, double-buffered. M%128==0, N%128==0, K%16==0.
#define SA_STRIDE 20
#define SW_STRIDE 136
template<int DO_GELU>
__global__ __launch_bounds__(256, 2) void gemm_tc_kernel(
        const float* __restrict__ A, const float* __restrict__ W,
        const float* __restrict__ bias, const float* __restrict__ resid,
        float* __restrict__ C, int M, int N, int K) {
    __shared__ float sA[2][128][SA_STRIDE];   // [m][k], k stride 20 (conflict-free frags)
    __shared__ float sW[2][16][SW_STRIDE];    // [k][n], n stride 136

    int tid = threadIdx.x;
    int lane = tid & 31, w = tid >> 5;
    int g2 = lane >> 2, c4 = lane & 3;        // fragment coords
    int wm = w & 3, wn = w >> 2;              // warp tile: rows wm*32, cols wn*64
    int m0 = blockIdx.y * 128, n0 = blockIdx.x * 128;

    // loader coords
    int ar = tid >> 1;               // A row 0..127
    int ac = (tid & 1) * 8;          // A k-offset 0 or 8
    int wr = tid >> 4;               // W k-row 0..15
    int wc = (tid & 15) * 8;         // W col

    const float* Aptr = A + (size_t)(m0 + ar) * K + ac;
    const float* Wptr = W + (size_t)wr * N + n0 + wc;

    int nc = K >> 4;

    float acc[2][8][4];
    #pragma unroll
    for (int mi = 0; mi < 2; mi++)
        #pragma unroll
        for (int ni = 0; ni < 8; ni++)
            #pragma unroll
            for (int r = 0; r < 4; r++) acc[mi][ni][r] = 0.f;

    // prologue: load + stage chunk 0
    float4 aR0 = *(const float4*)Aptr;
    float4 aR1 = *(const float4*)(Aptr + 4);
    float4 wR0 = *(const float4*)Wptr;
    float4 wR1 = *(const float4*)(Wptr + 4);
    {
        float4 t0, t1;
        t0.x = to_tf32(aR0.x); t0.y = to_tf32(aR0.y); t0.z = to_tf32(aR0.z); t0.w = to_tf32(aR0.w);
        t1.x = to_tf32(aR1.x); t1.y = to_tf32(aR1.y); t1.z = to_tf32(aR1.z); t1.w = to_tf32(aR1.w);
        *(float4*)&sA[0][ar][ac]     = t0;
        *(float4*)&sA[0][ar][ac + 4] = t1;
        t0.x = to_tf32(wR0.x); t0.y = to_tf32(wR0.y); t0.z = to_tf32(wR0.z); t0.w = to_tf32(wR0.w);
        t1.x = to_tf32(wR1.x); t1.y = to_tf32(wR1.y); t1.z = to_tf32(wR1.z); t1.w = to_tf32(wR1.w);
        *(float4*)&sW[0][wr][wc]     = t0;
        *(float4*)&sW[0][wr][wc + 4] = t1;
    }
    __syncthreads();

    for (int ch = 0; ch < nc; ch++) {
        int cur = ch & 1, nxt = cur ^ 1;
        if (ch + 1 < nc) {
            aR0 = *(const float4*)(Aptr + (ch + 1) * 16);
            aR1 = *(const float4*)(Aptr + (ch + 1) * 16 + 4);
            wR0 = *(const float4*)(Wptr + (size_t)(ch + 1) * 16 * N);
            wR1 = *(const float4*)(Wptr + (size_t)(ch + 1) * 16 * N + 4);
        }
        #pragma unroll
        for (int st = 0; st < 2; st++) {      // two k8 steps per chunk
            int k8 = st * 8;
            uint32_t af[2][4];
            #pragma unroll
            for (int mi = 0; mi < 2; mi++) {
                int r = wm * 32 + mi * 16 + g2;
                af[mi][0] = __float_as_uint(sA[cur][r][k8 + c4]);
                af[mi][1] = __float_as_uint(sA[cur][r + 8][k8 + c4]);
                af[mi][2] = __float_as_uint(sA[cur][r][k8 + c4 + 4]);
                af[mi][3] = __float_as_uint(sA[cur][r + 8][k8 + c4 + 4]);
            }
            uint32_t bf[8][2];
            #pragma unroll
            for (int ni = 0; ni < 8; ni++) {
                int col = wn * 64 + ni * 8 + g2;
                bf[ni][0] = __float_as_uint(sW[cur][k8 + c4][col]);
                bf[ni][1] = __float_as_uint(sW[cur][k8 + c4 + 4][col]);
            }
            #pragma unroll
            for (int mi = 0; mi < 2; mi++)
                #pragma unroll
                for (int ni = 0; ni < 8; ni++) {
                    asm volatile(
                        "mma.sync.aligned.m16n8k8.row.col.f32.tf32.tf32.f32 "
                        "{%0,%1,%2,%3}, {%4,%5,%6,%7}, {%8,%9}, {%0,%1,%2,%3};"
                        : "+f"(acc[mi][ni][0]), "+f"(acc[mi][ni][1]),
                          "+f"(acc[mi][ni][2]), "+f"(acc[mi][ni][3])
                        : "r"(af[mi][0]), "r"(af[mi][1]), "r"(af[mi][2]), "r"(af[mi][3]),
                          "r"(bf[ni][0]), "r"(bf[ni][1]));
                }
        }
        if (ch + 1 < nc) {
            float4 t0, t1;
            t0.x = to_tf32(aR0.x); t0.y = to_tf32(aR0.y); t0.z = to_tf32(aR0.z); t0.w = to_tf32(aR0.w);
            t1.x = to_tf32(aR1.x); t1.y = to_tf32(aR1.y); t1.z = to_tf32(aR1.z); t1.w = to_tf32(aR1.w);
            *(float4*)&sA[nxt][ar][ac]     = t0;
            *(float4*)&sA[nxt][ar][ac + 4] = t1;
            t0.x = to_tf32(wR0.x); t0.y = to_tf32(wR0.y); t0.z = to_tf32(wR0.z); t0.w = to_tf32(wR0.w);
            t1.x = to_tf32(wR1.x); t1.y = to_tf32(wR1.y); t1.z = to_tf32(wR1.z); t1.w = to_tf32(wR1.w);
            *(float4*)&sW[nxt][wr][wc]     = t0;
            *(float4*)&sW[nxt][wr][wc + 4] = t1;
        }
        __syncthreads();
    }

    // epilogue: acc -> C with bias (+resid) (+gelu); float2 stores
    #pragma unroll
    for (int mi = 0; mi < 2; mi++) {
        #pragma unroll
        for (int ni = 0; ni < 8; ni++) {
            int col = n0 + wn * 64 + ni * 8 + 2 * c4;
            float2 bv2 = *(const float2*)&bias[col];
            #pragma unroll
            for (int half = 0; half < 2; half++) {
                int row = m0 + wm * 32 + mi * 16 + g2 + half * 8;
                float2 v;
                v.x = acc[mi][ni][half * 2 + 0] + bv2.x;
                v.y = acc[mi][ni][half * 2 + 1] + bv2.y;
                size_t ci = (size_t)row * N + col;
                if (resid) {
                    float2 r2 = *(const float2*)&resid[ci];
                    v.x += r2.x; v.y += r2.y;
                }
                if (DO_GELU) {
                    float x = v.x, cc = x + 0.044715f * x * x * x;
                    v.x = 0.5f * x * (1.f + tanhf(0.7978845608028654f * cc));
                    x = v.y; cc = x + 0.044715f * x * x * x;
                    v.y = 0.5f * x * (1.f + tanhf(0.7978845608028654f * cc));
                }
                *(float2*)&C[ci] = v;
            }
        }
    }
}

// ---------------- attention: warp-per-query, rope fused, sparse-aware ------------
// QKV packed [M][384] (Q|K|V). One block per (bt, head), 8 warps.
__global__ __launch_bounds__(256) void attn2_kernel(
        const float* __restrict__ QKV, float* __restrict__ O, int L) {
    int h  = blockIdx.x & 7;
    int bt = blockIdx.x >> 3;
    __shared__ float Ksh[MAXL][20];
    __shared__ float Vsh[MAXL][16];
    __shared__ float esh[8][MAXL];
    __shared__ float invs[8];
    int tid = threadIdx.x;
    int w = tid >> 5, lane = tid & 31;

    if (tid < 8) invs[tid] = powf(100000.0f, -(float)tid / 8.0f);
    __syncthreads();

    // load K (with RoPE) and V into smem
    for (int i = tid; i < L * 8; i += 256) {
        int m = i >> 3, j = i & 7;
        size_t base = ((size_t)(bt * L + m)) * 384 + h * DHv + j;
        float k1 = QKV[base + 128], k2 = QKV[base + 128 + 8];
        float sv, cv;
        sincosf((float)m * invs[j], &sv, &cv);
        Ksh[m][j]     = k1 * cv - k2 * sv;
        Ksh[m][j + 8] = k1 * sv + k2 * cv;
        Vsh[m][j]     = QKV[base + 256];
        Vsh[m][j + 8] = QKV[base + 256 + 8];
    }
    __syncthreads();

    for (int lq = w; lq < L; lq += 8) {
        const float* qp = QKV + (size_t)(bt * L + lq) * 384 + h * DHv;
        float q[16];
        *(float4*)&q[0]  = *(const float4*)&qp[0];
        *(float4*)&q[4]  = *(const float4*)&qp[4];
        *(float4*)&q[8]  = *(const float4*)&qp[8];
        *(float4*)&q[12] = *(const float4*)&qp[12];
        float mys = 0.f, myc = 1.f;
        if (lane < 8) sincosf((float)lq * invs[lane], &mys, &myc);
        #pragma unroll
        for (int j = 0; j < 8; j++) {
            float cv = __shfl_sync(0xffffffffu, myc, j);
            float sv = __shfl_sync(0xffffffffu, mys, j);
            float q1 = q[j], q2 = q[j + 8];
            q[j]     = q1 * cv - q2 * sv;
            q[j + 8] = q1 * sv + q2 * cv;
        }

        if (lq >= NSPv) {
            int lo = lq - WINDOWv; if (lo < NSPv) lo = NSPv;
            int hi = lq + WINDOWv; if (hi > L - 1) hi = L - 1;
            int cnt = 6 + (hi - lo + 1);
            int m = (lane < 6) ? lane : (lo + lane - 6);
            if (m > L - 1) m = L - 1;
            bool act = lane < cnt;
            float s = -1e30f;
            if (act) {
                float d = 0.f;
                #pragma unroll
                for (int dd = 0; dd < 16; dd++) d += q[dd] * Ksh[m][dd];
                s = d * 0.25f;
            }
            float mx = s;
            #pragma unroll
            for (int o = 16; o > 0; o >>= 1) mx = fmaxf(mx, __shfl_xor_sync(0xffffffffu, mx, o));
            float e = act ? expf(s - mx) : 0.f;
            float sum = e;
            #pragma unroll
            for (int o = 16; o > 0; o >>= 1) sum += __shfl_xor_sync(0xffffffffu, sum, o);
            int d = lane & 15;
            float ov = 0.f;
            #pragma unroll
            for (int i = 0; i < 15; i++) {
                float ei = __shfl_sync(0xffffffffu, e, i);
                if (i < cnt) {
                    int mi = (i < 6) ? i : (lo + i - 6);
                    ov += ei * Vsh[mi][d];
                }
            }
            if (lane < 16)
                O[((size_t)(bt * L + lq)) * Ev + h * DHv + lane] = ov / sum;
        } else {
            float mx = -1e30f;
            for (int m = lane; m < L; m += 32) {
                float d = 0.f;
                #pragma unroll
                for (int dd = 0; dd < 16; dd++) d += q[dd] * Ksh[m][dd];
                d *= 0.25f;
                esh[w][m] = d;
                mx = fmaxf(mx, d);
            }
            #pragma unroll
            for (int o = 16; o > 0; o >>= 1) mx = fmaxf(mx, __shfl_xor_sync(0xffffffffu, mx, o));
            float sum = 0.f;
            for (int m = lane; m < L; m += 32) {
                float e = expf(esh[w][m] - mx);
                esh[w][m] = e;
                sum += e;
            }
            #pragma unroll
            for (int o = 16; o > 0; o >>= 1) sum += __shfl_xor_sync(0xffffffffu, sum, o);
            __syncwarp();
            int d = lane & 15, half = lane >> 4;
            float ov = 0.f;
            for (int m = half; m < L; m += 2) ov += esh[w][m] * Vsh[m][d];
            ov += __shfl_xor_sync(0xffffffffu, ov, 16);
            if (lane < 16)
                O[((size_t)(bt * L + lq)) * Ev + h * DHv + lane] = ov / sum;
            __syncwarp();
        }
    }
}

// ---------------- CLS accumulate across scales ----------------
__global__ void cls_acc_kernel(const float* __restrict__ X, float* __restrict__ acc,
                               int L, int init) {
    int idx = blockIdx.x * blockDim.x + threadIdx.x;
    if (idx >= BT * NUMCLSv * Ev) return;
    int e  = idx & (Ev - 1);
    int c  = (idx >> 7) & 3;
    int bt = idx >> 9;
    float v = X[((size_t)(bt * L + c)) * Ev + e];
    if (init) acc[idx] = v;
    else      acc[idx] += v;
}

// ---------------- final: mean over scales + LN + write ----------------
__global__ void final_kernel(const float* __restrict__ acc, const float* __restrict__ og,
                             const float* __restrict__ ob, float* __restrict__ out) {
    int row = blockIdx.x;
    int t = threadIdx.x;
    float v = acc[(size_t)row * Ev + t] * (1.f / 3.f);
    __shared__ float sh[4];
    float s = v;
    #pragma unroll
    for (int o = 16; o > 0; o >>= 1) s += __shfl_xor_sync(0xffffffffu, s, o);
    if ((t & 31) == 0) sh[t >> 5] = s;
    __syncthreads();
    float mean = (sh[0] + sh[1] + sh[2] + sh[3]) * (1.f / Ev);
    float d = v - mean;
    float s2 = d * d;
    #pragma unroll
    for (int o = 16; o > 0; o >>= 1) s2 += __shfl_xor_sync(0xffffffffu, s2, o);
    __syncthreads();
    if ((t & 31) == 0) sh[t >> 5] = s2;
    __syncthreads();
    float var = (sh[0] + sh[1] + sh[2] + sh[3]) * (1.f / Ev);
    out[(size_t)row * Ev + t] = d * rsqrtf(var + 1e-5f) * og[t] + ob[t];
}

// ---------------- host orchestration ----------------
extern "C" void kernel_launch(void* const* d_in, const int* in_sizes, int n_in,
                              void* d_out, int out_size) {
    const float* emb   = (const float*)d_in[0];
    const float* cls   = (const float*)d_in[1];
    const float* glb   = (const float*)d_in[2];
    const float* Wq    = (const float*)d_in[3];
    const float* bq    = (const float*)d_in[4];
    const float* Wk    = (const float*)d_in[5];
    const float* bk    = (const float*)d_in[6];
    const float* Wv    = (const float*)d_in[7];
    const float* bv    = (const float*)d_in[8];
    const float* Wo    = (const float*)d_in[9];
    const float* bo    = (const float*)d_in[10];
    const float* ln1g  = (const float*)d_in[11];
    const float* ln1b  = (const float*)d_in[12];
    const float* ln2g  = (const float*)d_in[13];
    const float* ln2b  = (const float*)d_in[14];
    const float* W1    = (const float*)d_in[15];
    const float* b1    = (const float*)d_in[16];
    const float* W2    = (const float*)d_in[17];
    const float* b2    = (const float*)d_in[18];
    const float* outg  = (const float*)d_in[19];
    const float* outb  = (const float*)d_in[20];
    float* out = (float*)d_out;

    float *X, *H, *QKV, *Ob, *FF, *CLSa, *Wp, *bp;
    cudaGetSymbolAddress((void**)&X,    g_X);
    cudaGetSymbolAddress((void**)&H,    g_H);
    cudaGetSymbolAddress((void**)&QKV,  g_QKV);
    cudaGetSymbolAddress((void**)&Ob,   g_Ob);
    cudaGetSymbolAddress((void**)&FF,   g_FF);
    cudaGetSymbolAddress((void**)&CLSa, g_CLS);
    cudaGetSymbolAddress((void**)&Wp,   g_Wqkv);
    cudaGetSymbolAddress((void**)&bp,   g_bqkv);

    static const int GS[3] = {1, 4, 8};
    for (int s = 0; s < 3; s++) {
        int g = GS[s];
        int Kgrp = HFEATv / g;
        int L = NSPv + Kgrp;
        int M = BT * L;

        {
            int total = M * Ev;
            build_x_kernel<<<(total + 255) / 256, 256>>>(emb, cls, glb, X, L, g);
        }

        for (int l = 0; l < NLAYERSv; l++) {
            int wi = s * NLAYERSv + l;
            const float* wq = Wq + (size_t)wi * Ev * Ev;
            const float* wk = Wk + (size_t)wi * Ev * Ev;
            const float* wv = Wv + (size_t)wi * Ev * Ev;
            const float* wo = Wo + (size_t)wi * Ev * Ev;
            const float* w1 = W1 + (size_t)wi * Ev * Fv;
            const float* w2 = W2 + (size_t)wi * Fv * Ev;

            pack_qkv_kernel<<<(Ev * 384 + 255) / 256, 256>>>(
                wq, wk, wv, bq + (size_t)wi * Ev, bk + (size_t)wi * Ev,
                bv + (size_t)wi * Ev, Wp, bp);

            ln_kernel<<<M, 128>>>(X, ln1g + (size_t)wi * Ev, ln1b + (size_t)wi * Ev, H);

            // fused QKV gemm: [M,128] @ [128,384]
            {
                dim3 gr(384 / 128, M / 128);
                gemm_tc_kernel<0><<<gr, 256>>>(H, Wp, bp, nullptr, QKV, M, 384, Ev);
            }

            attn2_kernel<<<BT * NHEADv, 256>>>(QKV, Ob, L);

            {
                dim3 gr(1, M / 128);
                gemm_tc_kernel<0><<<gr, 256>>>(Ob, wo, bo + (size_t)wi * Ev, X, X, M, Ev, Ev);
            }

            ln_kernel<<<M, 128>>>(X, ln2g + (size_t)wi * Ev, ln2b + (size_t)wi * Ev, H);

            {
                dim3 gr(Fv / 128, M / 128);
                gemm_tc_kernel<1><<<gr, 256>>>(H, w1, b1 + (size_t)wi * Fv, nullptr, FF, M, Fv, Ev);
            }
            {
                dim3 gr(1, M / 128);
                gemm_tc_kernel<0><<<gr, 256>>>(FF, w2, b2 + (size_t)wi * Ev, X, X, M, Ev, Fv);
            }
        }

        {
            int total = BT * NUMCLSv * Ev;
            cls_acc_kernel<<<(total + 255) / 256, 256>>>(X, CLSa, L, s == 0 ? 1 : 0);
        }
    }

    final_kernel<<<BT * NUMCLSv, 128>>>(CLSa, outg, outb, out);
}

// round 13
// speedup vs baseline: 3.4566x; 1.0692x over previous
#include <cuda_runtime.h>
#include <math.h>
#include <stdint.h>

#define Bv 32
#define Tv 8
#define BT 256
#define Ev 128
#define Fv 512
#define NHEADv 8
#define DHv 16
#define NSPv 6
#define NUMCLSv 4
#define HFEATv 128
#define WINDOWv 4
#define NLAYERSv 2
#define MAXL 134
#define MAXM (BT*MAXL)

// ---------------- scratch (device globals; no allocation allowed) ----------------
__device__ float g_X[MAXM*Ev];
__device__ float g_QKV[MAXM*384];
__device__ float g_Ob[MAXM*Ev];
__device__ float g_FF[MAXM*Fv];
__device__ float g_CLS[BT*NUMCLSv*Ev];
__device__ float g_Wqkv[Ev*384];
__device__ float g_bqkv[384];
__device__ float g_mu[MAXM];
__device__ float g_rs[MAXM];

// ---------------- helpers ----------------
__device__ __forceinline__ float to_tf32(float x) {
    uint32_t u;
    asm("cvt.rna.tf32.f32 %0, %1;" : "=r"(u) : "f"(x));
    return __uint_as_float(u);
}

// ---------------- build sequence: specials + grouped mean pooling ----------------
__global__ void build_x_kernel(const float* __restrict__ emb,
                               const float* __restrict__ cls,
                               const float* __restrict__ glb,
                               float* __restrict__ X, int L, int g) {
    int idx = blockIdx.x * blockDim.x + threadIdx.x;
    int total = BT * L * Ev;
    if (idx >= total) return;
    int e  = idx & (Ev - 1);
    int l  = (idx >> 7) % L;
    int bt = idx / (L * Ev);
    float v;
    if (l < NUMCLSv) {
        v = cls[l * Ev + e];
    } else if (l < NSPv) {
        v = glb[(l - NUMCLSv) * Ev + e];
    } else {
        int k = l - NSPv;
        const float* base = emb + ((size_t)bt * (NSPv + HFEATv) + NSPv + (size_t)k * g) * Ev + e;
        float s = 0.f;
        for (int j = 0; j < g; j++) s += base[(size_t)j * Ev];
        v = s / (float)g;
    }
    X[idx] = v;
}

// ---------------- per-row LN stats: mean + rstd (warp per row, 8 rows/block) -----
__global__ void ln_stats_kernel(const float* __restrict__ X,
                                float* __restrict__ mu, float* __restrict__ rs, int M) {
    int row = blockIdx.x * 8 + (threadIdx.x >> 5);
    int lane = threadIdx.x & 31;
    if (row >= M) return;
    float4 v = *(const float4*)&X[(size_t)row * Ev + lane * 4];
    float s = v.x + v.y + v.z + v.w;
    #pragma unroll
    for (int o = 16; o > 0; o >>= 1) s += __shfl_xor_sync(0xffffffffu, s, o);
    float mean = s * (1.f / Ev);
    float d0 = v.x - mean, d1 = v.y - mean, d2 = v.z - mean, d3 = v.w - mean;
    float s2 = d0 * d0 + d1 * d1 + d2 * d2 + d3 * d3;
    #pragma unroll
    for (int o = 16; o > 0; o >>= 1) s2 += __shfl_xor_sync(0xffffffffu, s2, o);
    if (lane == 0) {
        mu[row] = mean;
        rs[row] = rsqrtf(s2 * (1.f / Ev) + 1e-5f);
    }
}

// ---------------- pack QKV weights/biases into one [E,384] matrix ----------------
__global__ void pack_qkv_kernel(const float* __restrict__ Wq, const float* __restrict__ Wk,
                                const float* __restrict__ Wv, const float* __restrict__ bq,
                                const float* __restrict__ bk, const float* __restrict__ bv,
                                float* __restrict__ Wp, float* __restrict__ bp) {
    int idx = blockIdx.x * blockDim.x + threadIdx.x;
    if (idx < 384) {
        int which = idx >> 7, col = idx & 127;
        bp[idx] = (which == 0) ? bq[col] : (which == 1) ? bk[col] : bv[col];
    }
    if (idx < Ev * 384) {
        int k = idx / 384, n = idx % 384;
        int which = n >> 7, col = n & 127;
        const float* src = (which == 0) ? Wq : (which == 1) ? Wk : Wv;
        Wp[idx] = src[k * Ev + col];
    }
}

// ---------------- TF32 tensor-core GEMM, LN fused on A-load -----------------------
// C[M,N] = LN?(A)[M,K] @ W[K,N] + bias (+resid) (opt GELU).
// Block tile 64x128, 8 warps (warp 32x32 = 2 m16 x 4 n8, mma.m16n8k8.tf32).
// K chunked by 16, double-buffered. M%64==0, N%128==0, K%16==0.
#define SA_STRIDE 20
#define SW_STRIDE 136
template<int DO_GELU, int DO_LN>
__global__ __launch_bounds__(256, 3) void gemm_tc_kernel(
        const float* __restrict__ A, const float* __restrict__ W,
        const float* __restrict__ bias, const float* __restrict__ resid,
        const float* __restrict__ lnG, const float* __restrict__ lnB,
        const float* __restrict__ mu, const float* __restrict__ rs,
        float* __restrict__ C, int M, int N, int K) {
    __shared__ float sA[2][64][SA_STRIDE];    // [m][k], stride 20 (conflict-free frags)
    __shared__ float sW[2][16][SW_STRIDE];    // [k][n], stride 136

    int tid = threadIdx.x;
    int lane = tid & 31, w = tid >> 5;
    int g2 = lane >> 2, c4 = lane & 3;        // fragment coords
    int wm = w & 1, wn = w >> 1;              // warp tile: rows wm*32, cols wn*32
    int m0 = blockIdx.y * 64, n0 = blockIdx.x * 128;

    // loader coords
    int ar = tid >> 2;               // A row 0..63
    int ac = (tid & 3) * 4;          // A k-offset 0/4/8/12
    int wr = tid >> 4;               // W k-row 0..15
    int wc = (tid & 15) * 8;         // W col

    const float* Aptr = A + (size_t)(m0 + ar) * K + ac;
    const float* Wptr = W + (size_t)wr * N + n0 + wc;

    float rowMu = 0.f, rowRs = 1.f;
    if (DO_LN) { rowMu = mu[m0 + ar]; rowRs = rs[m0 + ar]; }

    int nc = K >> 4;

    float acc[2][4][4];
    #pragma unroll
    for (int mi = 0; mi < 2; mi++)
        #pragma unroll
        for (int ni = 0; ni < 4; ni++)
            #pragma unroll
            for (int r = 0; r < 4; r++) acc[mi][ni][r] = 0.f;

    // prologue: load + stage chunk 0
    float4 aR = *(const float4*)Aptr;
    float4 wR0 = *(const float4*)Wptr;
    float4 wR1 = *(const float4*)(Wptr + 4);
    {
        float4 t = aR;
        if (DO_LN) {
            float4 gg = *(const float4*)&lnG[ac];
            float4 bb = *(const float4*)&lnB[ac];
            t.x = (t.x - rowMu) * rowRs * gg.x + bb.x;
            t.y = (t.y - rowMu) * rowRs * gg.y + bb.y;
            t.z = (t.z - rowMu) * rowRs * gg.z + bb.z;
            t.w = (t.w - rowMu) * rowRs * gg.w + bb.w;
        }
        t.x = to_tf32(t.x); t.y = to_tf32(t.y); t.z = to_tf32(t.z); t.w = to_tf32(t.w);
        *(float4*)&sA[0][ar][ac] = t;
        float4 u0, u1;
        u0.x = to_tf32(wR0.x); u0.y = to_tf32(wR0.y); u0.z = to_tf32(wR0.z); u0.w = to_tf32(wR0.w);
        u1.x = to_tf32(wR1.x); u1.y = to_tf32(wR1.y); u1.z = to_tf32(wR1.z); u1.w = to_tf32(wR1.w);
        *(float4*)&sW[0][wr][wc]     = u0;
        *(float4*)&sW[0][wr][wc + 4] = u1;
    }
    __syncthreads();

    for (int ch = 0; ch < nc; ch++) {
        int cur = ch & 1, nxt = cur ^ 1;
        if (ch + 1 < nc) {
            aR  = *(const float4*)(Aptr + (ch + 1) * 16);
            wR0 = *(const float4*)(Wptr + (size_t)(ch + 1) * 16 * N);
            wR1 = *(const float4*)(Wptr + (size_t)(ch + 1) * 16 * N + 4);
        }
        #pragma unroll
        for (int st = 0; st < 2; st++) {      // two k8 steps per chunk
            int k8 = st * 8;
            uint32_t af[2][4];
            #pragma unroll
            for (int mi = 0; mi < 2; mi++) {
                int r = wm * 32 + mi * 16 + g2;
                af[mi][0] = __float_as_uint(sA[cur][r][k8 + c4]);
                af[mi][1] = __float_as_uint(sA[cur][r + 8][k8 + c4]);
                af[mi][2] = __float_as_uint(sA[cur][r][k8 + c4 + 4]);
                af[mi][3] = __float_as_uint(sA[cur][r + 8][k8 + c4 + 4]);
            }
            uint32_t bf[4][2];
            #pragma unroll
            for (int ni = 0; ni < 4; ni++) {
                int col = wn * 32 + ni * 8 + g2;
                bf[ni][0] = __float_as_uint(sW[cur][k8 + c4][col]);
                bf[ni][1] = __float_as_uint(sW[cur][k8 + c4 + 4][col]);
            }
            #pragma unroll
            for (int mi = 0; mi < 2; mi++)
                #pragma unroll
                for (int ni = 0; ni < 4; ni++) {
                    asm volatile(
                        "mma.sync.aligned.m16n8k8.row.col.f32.tf32.tf32.f32 "
                        "{%0,%1,%2,%3}, {%4,%5,%6,%7}, {%8,%9}, {%0,%1,%2,%3};"
                        : "+f"(acc[mi][ni][0]), "+f"(acc[mi][ni][1]),
                          "+f"(acc[mi][ni][2]), "+f"(acc[mi][ni][3])
                        : "r"(af[mi][0]), "r"(af[mi][1]), "r"(af[mi][2]), "r"(af[mi][3]),
                          "r"(bf[ni][0]), "r"(bf[ni][1]));
                }
        }
        if (ch + 1 < nc) {
            float4 t = aR;
            if (DO_LN) {
                float4 gg = *(const float4*)&lnG[(ch + 1) * 16 + ac];
                float4 bb = *(const float4*)&lnB[(ch + 1) * 16 + ac];
                t.x = (t.x - rowMu) * rowRs * gg.x + bb.x;
                t.y = (t.y - rowMu) * rowRs * gg.y + bb.y;
                t.z = (t.z - rowMu) * rowRs * gg.z + bb.z;
                t.w = (t.w - rowMu) * rowRs * gg.w + bb.w;
            }
            t.x = to_tf32(t.x); t.y = to_tf32(t.y); t.z = to_tf32(t.z); t.w = to_tf32(t.w);
            *(float4*)&sA[nxt][ar][ac] = t;
            float4 u0, u1;
            u0.x = to_tf32(wR0.x); u0.y = to_tf32(wR0.y); u0.z = to_tf32(wR0.z); u0.w = to_tf32(wR0.w);
            u1.x = to_tf32(wR1.x); u1.y = to_tf32(wR1.y); u1.z = to_tf32(wR1.z); u1.w = to_tf32(wR1.w);
            *(float4*)&sW[nxt][wr][wc]     = u0;
            *(float4*)&sW[nxt][wr][wc + 4] = u1;
        }
        __syncthreads();
    }

    // epilogue: acc -> C with bias (+resid) (+gelu); float2 stores
    #pragma unroll
    for (int mi = 0; mi < 2; mi++) {
        #pragma unroll
        for (int ni = 0; ni < 4; ni++) {
            int col = n0 + wn * 32 + ni * 8 + 2 * c4;
            float2 bv2 = *(const float2*)&bias[col];
            #pragma unroll
            for (int half = 0; half < 2; half++) {
                int row = m0 + wm * 32 + mi * 16 + g2 + half * 8;
                float2 v;
                v.x = acc[mi][ni][half * 2 + 0] + bv2.x;
                v.y = acc[mi][ni][half * 2 + 1] + bv2.y;
                size_t ci = (size_t)row * N + col;
                if (resid) {
                    float2 r2 = *(const float2*)&resid[ci];
                    v.x += r2.x; v.y += r2.y;
                }
                if (DO_GELU) {
                    float x = v.x, cc = x + 0.044715f * x * x * x;
                    v.x = 0.5f * x * (1.f + tanhf(0.7978845608028654f * cc));
                    x = v.y; cc = x + 0.044715f * x * x * x;
                    v.y = 0.5f * x * (1.f + tanhf(0.7978845608028654f * cc));
                }
                *(float2*)&C[ci] = v;
            }
        }
    }
}

// ---------------- attention: warp-per-query, rope fused, sparse-aware ------------
// QKV packed [M][384] (Q|K|V). One block per (bt, head), 8 warps.
__global__ __launch_bounds__(256) void attn2_kernel(
        const float* __restrict__ QKV, float* __restrict__ O, int L) {
    int h  = blockIdx.x & 7;
    int bt = blockIdx.x >> 3;
    __shared__ float Ksh[MAXL][20];
    __shared__ float Vsh[MAXL][16];
    __shared__ float esh[8][MAXL];
    __shared__ float invs[8];
    int tid = threadIdx.x;
    int w = tid >> 5, lane = tid & 31;

    if (tid < 8) invs[tid] = powf(100000.0f, -(float)tid / 8.0f);
    __syncthreads();

    // load K (with RoPE) and V into smem
    for (int i = tid; i < L * 8; i += 256) {
        int m = i >> 3, j = i & 7;
        size_t base = ((size_t)(bt * L + m)) * 384 + h * DHv + j;
        float k1 = QKV[base + 128], k2 = QKV[base + 128 + 8];
        float sv, cv;
        sincosf((float)m * invs[j], &sv, &cv);
        Ksh[m][j]     = k1 * cv - k2 * sv;
        Ksh[m][j + 8] = k1 * sv + k2 * cv;
        Vsh[m][j]     = QKV[base + 256];
        Vsh[m][j + 8] = QKV[base + 256 + 8];
    }
    __syncthreads();

    for (int lq = w; lq < L; lq += 8) {
        const float* qp = QKV + (size_t)(bt * L + lq) * 384 + h * DHv;
        float q[16];
        *(float4*)&q[0]  = *(const float4*)&qp[0];
        *(float4*)&q[4]  = *(const float4*)&qp[4];
        *(float4*)&q[8]  = *(const float4*)&qp[8];
        *(float4*)&q[12] = *(const float4*)&qp[12];
        float mys = 0.f, myc = 1.f;
        if (lane < 8) sincosf((float)lq * invs[lane], &mys, &myc);
        #pragma unroll
        for (int j = 0; j < 8; j++) {
            float cv = __shfl_sync(0xffffffffu, myc, j);
            float sv = __shfl_sync(0xffffffffu, mys, j);
            float q1 = q[j], q2 = q[j + 8];
            q[j]     = q1 * cv - q2 * sv;
            q[j + 8] = q1 * sv + q2 * cv;
        }

        if (lq >= NSPv) {
            int lo = lq - WINDOWv; if (lo < NSPv) lo = NSPv;
            int hi = lq + WINDOWv; if (hi > L - 1) hi = L - 1;
            int cnt = 6 + (hi - lo + 1);
            int m = (lane < 6) ? lane : (lo + lane - 6);
            if (m > L - 1) m = L - 1;
            bool act = lane < cnt;
            float s = -1e30f;
            if (act) {
                float d = 0.f;
                #pragma unroll
                for (int dd = 0; dd < 16; dd++) d += q[dd] * Ksh[m][dd];
                s = d * 0.25f;
            }
            float mx = s;
            #pragma unroll
            for (int o = 16; o > 0; o >>= 1) mx = fmaxf(mx, __shfl_xor_sync(0xffffffffu, mx, o));
            float e = act ? expf(s - mx) : 0.f;
            float sum = e;
            #pragma unroll
            for (int o = 16; o > 0; o >>= 1) sum += __shfl_xor_sync(0xffffffffu, sum, o);
            int d = lane & 15;
            float ov = 0.f;
            #pragma unroll
            for (int i = 0; i < 15; i++) {
                float ei = __shfl_sync(0xffffffffu, e, i);
                if (i < cnt) {
                    int mi = (i < 6) ? i : (lo + i - 6);
                    ov += ei * Vsh[mi][d];
                }
            }
            if (lane < 16)
                O[((size_t)(bt * L + lq)) * Ev + h * DHv + lane] = ov / sum;
        } else {
            float mx = -1e30f;
            for (int m = lane; m < L; m += 32) {
                float d = 0.f;
                #pragma unroll
                for (int dd = 0; dd < 16; dd++) d += q[dd] * Ksh[m][dd];
                d *= 0.25f;
                esh[w][m] = d;
                mx = fmaxf(mx, d);
            }
            #pragma unroll
            for (int o = 16; o > 0; o >>= 1) mx = fmaxf(mx, __shfl_xor_sync(0xffffffffu, mx, o));
            float sum = 0.f;
            for (int m = lane; m < L; m += 32) {
                float e = expf(esh[w][m] - mx);
                esh[w][m] = e;
                sum += e;
            }
            #pragma unroll
            for (int o = 16; o > 0; o >>= 1) sum += __shfl_xor_sync(0xffffffffu, sum, o);
            __syncwarp();
            int d = lane & 15, half = lane >> 4;
            float ov = 0.f;
            for (int m = half; m < L; m += 2) ov += esh[w][m] * Vsh[m][d];
            ov += __shfl_xor_sync(0xffffffffu, ov, 16);
            if (lane < 16)
                O[((size_t)(bt * L + lq)) * Ev + h * DHv + lane] = ov / sum;
            __syncwarp();
        }
    }
}

// ---------------- CLS accumulate across scales ----------------
__global__ void cls_acc_kernel(const float* __restrict__ X, float* __restrict__ acc,
                               int L, int init) {
    int idx = blockIdx.x * blockDim.x + threadIdx.x;
    if (idx >= BT * NUMCLSv * Ev) return;
    int e  = idx & (Ev - 1);
    int c  = (idx >> 7) & 3;
    int bt = idx >> 9;
    float v = X[((size_t)(bt * L + c)) * Ev + e];
    if (init) acc[idx] = v;
    else      acc[idx] += v;
}

// ---------------- final: mean over scales + LN + write ----------------
__global__ void final_kernel(const float* __restrict__ acc, const float* __restrict__ og,
                             const float* __restrict__ ob, float* __restrict__ out) {
    int row = blockIdx.x;
    int t = threadIdx.x;
    float v = acc[(size_t)row * Ev + t] * (1.f / 3.f);
    __shared__ float sh[4];
    float s = v;
    #pragma unroll
    for (int o = 16; o > 0; o >>= 1) s += __shfl_xor_sync(0xffffffffu, s, o);
    if ((t & 31) == 0) sh[t >> 5] = s;
    __syncthreads();
    float mean = (sh[0] + sh[1] + sh[2] + sh[3]) * (1.f / Ev);
    float d = v - mean;
    float s2 = d * d;
    #pragma unroll
    for (int o = 16; o > 0; o >>= 1) s2 += __shfl_xor_sync(0xffffffffu, s2, o);
    __syncthreads();
    if ((t & 31) == 0) sh[t >> 5] = s2;
    __syncthreads();
    float var = (sh[0] + sh[1] + sh[2] + sh[3]) * (1.f / Ev);
    out[(size_t)row * Ev + t] = d * rsqrtf(var + 1e-5f) * og[t] + ob[t];
}

// ---------------- host orchestration ----------------
extern "C" void kernel_launch(void* const* d_in, const int* in_sizes, int n_in,
                              void* d_out, int out_size) {
    const float* emb   = (const float*)d_in[0];
    const float* cls   = (const float*)d_in[1];
    const float* glb   = (const float*)d_in[2];
    const float* Wq    = (const float*)d_in[3];
    const float* bq    = (const float*)d_in[4];
    const float* Wk    = (const float*)d_in[5];
    const float* bk    = (const float*)d_in[6];
    const float* Wv    = (const float*)d_in[7];
    const float* bv    = (const float*)d_in[8];
    const float* Wo    = (const float*)d_in[9];
    const float* bo    = (const float*)d_in[10];
    const float* ln1g  = (const float*)d_in[11];
    const float* ln1b  = (const float*)d_in[12];
    const float* ln2g  = (const float*)d_in[13];
    const float* ln2b  = (const float*)d_in[14];
    const float* W1    = (const float*)d_in[15];
    const float* b1    = (const float*)d_in[16];
    const float* W2    = (const float*)d_in[17];
    const float* b2    = (const float*)d_in[18];
    const float* outg  = (const float*)d_in[19];
    const float* outb  = (const float*)d_in[20];
    float* out = (float*)d_out;

    float *X, *QKV, *Ob, *FF, *CLSa, *Wp, *bp, *mu, *rs;
    cudaGetSymbolAddress((void**)&X,    g_X);
    cudaGetSymbolAddress((void**)&QKV,  g_QKV);
    cudaGetSymbolAddress((void**)&Ob,   g_Ob);
    cudaGetSymbolAddress((void**)&FF,   g_FF);
    cudaGetSymbolAddress((void**)&CLSa, g_CLS);
    cudaGetSymbolAddress((void**)&Wp,   g_Wqkv);
    cudaGetSymbolAddress((void**)&bp,   g_bqkv);
    cudaGetSymbolAddress((void**)&mu,   g_mu);
    cudaGetSymbolAddress((void**)&rs,   g_rs);

    static const int GS[3] = {1, 4, 8};
    for (int s = 0; s < 3; s++) {
        int g = GS[s];
        int Kgrp = HFEATv / g;
        int L = NSPv + Kgrp;
        int M = BT * L;

        {
            int total = M * Ev;
            build_x_kernel<<<(total + 255) / 256, 256>>>(emb, cls, glb, X, L, g);
        }

        for (int l = 0; l < NLAYERSv; l++) {
            int wi = s * NLAYERSv + l;
            const float* wq = Wq + (size_t)wi * Ev * Ev;
            const float* wk = Wk + (size_t)wi * Ev * Ev;
            const float* wv = Wv + (size_t)wi * Ev * Ev;
            const float* wo = Wo + (size_t)wi * Ev * Ev;
            const float* w1 = W1 + (size_t)wi * Ev * Fv;
            const float* w2 = W2 + (size_t)wi * Fv * Ev;

            pack_qkv_kernel<<<(Ev * 384 + 255) / 256, 256>>>(
                wq, wk, wv, bq + (size_t)wi * Ev, bk + (size_t)wi * Ev,
                bv + (size_t)wi * Ev, Wp, bp);

            // LN1 stats + fused QKV gemm: [M,128] @ [128,384] with LN applied on A-load
            ln_stats_kernel<<<M / 8, 256>>>(X, mu, rs, M);
            {
                dim3 gr(384 / 128, M / 64);
                gemm_tc_kernel<0, 1><<<gr, 256>>>(X, Wp, bp, nullptr,
                    ln1g + (size_t)wi * Ev, ln1b + (size_t)wi * Ev, mu, rs,
                    QKV, M, 384, Ev);
            }

            attn2_kernel<<<BT * NHEADv, 256>>>(QKV, Ob, L);

            // O-proj + residual -> X
            {
                dim3 gr(1, M / 64);
                gemm_tc_kernel<0, 0><<<gr, 256>>>(Ob, wo, bo + (size_t)wi * Ev, X,
                    nullptr, nullptr, nullptr, nullptr, X, M, Ev, Ev);
            }

            // LN2 stats + fused FF1 gemm (+GELU)
            ln_stats_kernel<<<M / 8, 256>>>(X, mu, rs, M);
            {
                dim3 gr(Fv / 128, M / 64);
                gemm_tc_kernel<1, 1><<<gr, 256>>>(X, w1, b1 + (size_t)wi * Fv, nullptr,
                    ln2g + (size_t)wi * Ev, ln2b + (size_t)wi * Ev, mu, rs,
                    FF, M, Fv, Ev);
            }
            // FF2 + residual -> X
            {
                dim3 gr(1, M / 64);
                gemm_tc_kernel<0, 0><<<gr, 256>>>(FF, w2, b2 + (size_t)wi * Ev, X,
                    nullptr, nullptr, nullptr, nullptr, X, M, Ev, Fv);
            }
        }

        {
            int total = BT * NUMCLSv * Ev;
            cls_acc_kernel<<<(total + 255) / 256, 256>>>(X, CLSa, L, s == 0 ? 1 : 0);
        }
    }

    final_kernel<<<BT * NUMCLSv, 128>>>(CLSa, outg, outb, out);
}